// round 12
// baseline (speedup 1.0000x reference)
#include <cuda_runtime.h>
#include <cuda_fp16.h>
#include <cstdint>
#include <cstddef>

// ---------------------------------------------------------------------------
// Problem constants
// ---------------------------------------------------------------------------
namespace {
constexpr int BATCH = 8;
constexpr int FI    = 256;
constexpr int FO    = 512;
constexpr int HW    = 256;     // input H = W
constexpr int OHW   = 128;     // output H = W
constexpr int KTOT  = FI * 9;  // 2304 (GEMM K, reordered k' = r*256 + fi)
constexpr int PROWS = 129;     // phase rows (h2 = 0..128)
constexpr int PW    = 128;     // phase cols (w2)
}

// Scratch (device globals; no cudaMalloc allowed).
__device__ __half g_P2[(size_t)6 * BATCH * PROWS * PW * FI];   // ~406 MB
__device__ __half g_Wh2[(size_t)FO * KTOT];

// ---------------------------------------------------------------------------
// Pass 1 (v9): 512-thread blocks, ONE channel per warp (16 warps = 16 fi),
// 16-row h-groups, full row-pair load batching, 16-fi cells -> full-sector
// 32B stores. Low regs (cap 64) -> 2 blocks/SM = 32 warps/SM.
// Grid (17, 16, 8).
// ---------------------------------------------------------------------------
__global__ void __launch_bounds__(512, 2)
fir9_kernel(const float* __restrict__ x, const float* __restrict__ fir) {
    __shared__ __half S[6 * 128 * 18];   // 27648 B; [slot][w2][fl(pad 18)]

    const int tid  = threadIdx.x;
    const int lane = tid & 31;
    const int wid  = tid >> 5;           // 0..15  (= fl)
    const int j  = blockIdx.x;           // 0..16 (h0 = 16j)
    const int fc = blockIdx.y;           // 0..15
    const int b  = blockIdx.z;           // 0..7
    const int h0 = 16 * j;

    const float f0 = fir[0]  + fir[1]  + fir[2]  + fir[3];
    const float f1 = fir[4]  + fir[5]  + fir[6]  + fir[7];
    const float f2 = fir[8]  + fir[9]  + fir[10] + fir[11];
    const float f3 = fir[12] + fir[13] + fir[14] + fir[15];

    const int c8 = lane * 8;
    const float* xc = x + (size_t)(b * FI + fc * 16 + wid) * (HW * HW);

    auto ldrow = [&](int h, float (&r)[8]) {
        if ((unsigned)h < (unsigned)HW) {
            const float4 a  = __ldg((const float4*)(xc + h * HW + c8));
            const float4 b2 = __ldg((const float4*)(xc + h * HW + c8 + 4));
            r[0]=a.x; r[1]=a.y; r[2]=a.z; r[3]=a.w;
            r[4]=b2.x; r[5]=b2.y; r[6]=b2.z; r[7]=b2.w;
        } else {
            #pragma unroll
            for (int q = 0; q < 8; q++) r[q] = 0.0f;
        }
    };

    // hist rows: h-2, h-1, h relative to next output row
    float hist[3][8];
    ldrow(h0 - 2, hist[0]);
    ldrow(h0 - 1, hist[1]);
    ldrow(h0,     hist[2]);

    for (int p = 0; p < 8; p++) {
        const int hb = h0 + 2 * p;
        const bool any = hb <= 256;
        if (any) {
            // batch both row loads before any math (4 x float4 in flight)
            float p1[8], p2[8];
            ldrow(hb + 1, p1);
            ldrow(hb + 2, p2);

            #pragma unroll
            for (int rr = 0; rr < 2; rr++) {
                const int h = hb + rr;
                if (h > 256) break;      // warp-uniform
                float V[8];
                #pragma unroll
                for (int q = 0; q < 8; q++) {
                    V[q] = (rr == 0)
                        ? f0 * hist[0][q] + f1 * hist[1][q]
                        + f2 * hist[2][q] + f3 * p1[q]
                        : f0 * hist[1][q] + f1 * hist[2][q]
                        + f2 * p1[q]     + f3 * p2[q];
                }
                float vm2 = __shfl_up_sync(0xffffffffu, V[6], 1);
                float vm1 = __shfl_up_sync(0xffffffffu, V[7], 1);
                float vp1 = __shfl_down_sync(0xffffffffu, V[0], 1);
                if (lane == 0)  { vm2 = 0.0f; vm1 = 0.0f; }
                if (lane == 31) { vp1 = 0.0f; }
                float Vf[11];
                Vf[0] = vm2; Vf[1] = vm1;
                #pragma unroll
                for (int q = 0; q < 8; q++) Vf[2 + q] = V[q];
                Vf[10] = vp1;

                const int a = h & 1;
                #pragma unroll
                for (int q = 0; q < 8; q++) {
                    const float y = f0 * Vf[q] + f1 * Vf[q + 1]
                                  + f2 * Vf[q + 2] + f3 * Vf[q + 3];
                    const __half hv = __float2half_rn(y);
                    const int w  = c8 + q;
                    const int w2 = w >> 1;
                    if (!(q & 1)) {
                        S[((a * 3 + 0) * 128 + w2) * 18 + wid] = hv;        // kw=0
                        if (w >= 2)
                            S[((a * 3 + 2) * 128 + (w2 - 1)) * 18 + wid] = hv; // kw=2
                    } else {
                        S[((a * 3 + 1) * 128 + w2) * 18 + wid] = hv;        // kw=1
                    }
                }
                if (lane == 31) {  // w = 256 -> kw=2 plane, w2 = 127
                    const float y2 = f0 * V[6] + f1 * V[7];
                    S[((a * 3 + 2) * 128 + 127) * 18 + wid] = __float2half_rn(y2);
                }
            }
            // single history shift per step (advance 2 rows)
            #pragma unroll
            for (int q = 0; q < 8; q++) {
                hist[0][q] = hist[2][q];
                hist[1][q] = p1[q];
                hist[2][q] = p2[q];
            }
        }
        __syncthreads();
        if (any) {
            const int h2 = 8 * j + p;
            const uint32_t* Sw = (const uint32_t*)S;
            #pragma unroll
            for (int i = 0; i < 12; i++) {
                const int u    = i * 512 + tid;        // 0..6143
                const int slot = u >> 10;
                const int rem  = u & 1023;
                const int w2   = rem >> 3;
                const int q    = rem & 7;
                const int a    = slot / 3;
                const int kw   = slot - a * 3;
                if (hb + a > 256) continue;
                const int pi = kw * 2 + a;
                const size_t g = ((((size_t)pi * BATCH + b) * PROWS + h2) * PW + w2) * FI
                               + fc * 16 + q * 2;
                *(uint32_t*)&g_P2[g] = Sw[(slot * 128 + w2) * 9 + q];
            }
        }
        __syncthreads();
    }
}

// ---------------------------------------------------------------------------
// Pass 1b: weights -> fp16, K reorder
// ---------------------------------------------------------------------------
__global__ void wcvt2_kernel(const float* __restrict__ w) {
    const int i = blockIdx.x * 256 + threadIdx.x;
    if (i >= FO * KTOT) return;
    const int fo = i / KTOT;
    const int k  = i - fo * KTOT;
    const int r  = k >> 8;
    const int fi = k & 255;
    g_Wh2[i] = __float2half_rn(w[((size_t)(fo * FI + fi)) * 9 + r] * (1.0f / 48.0f));
}

// ---------------------------------------------------------------------------
// Pass 2 (v10, unchanged from best): HMMA implicit GEMM, CTA 128x128,
// 4 warps (64x64), BK=64, 3 stages, 2 CTAs/SM, unrolled stage indices.
// ---------------------------------------------------------------------------
namespace {
constexpr int NIT   = 36;
constexpr int NSTG  = 3;
constexpr int A_STG = 128 * 128;
constexpr int B_STG = 128 * 128;
constexpr size_t GEMM_SMEM = (size_t)NSTG * (A_STG + B_STG);  // 98304
}

__device__ __forceinline__ void cp16(uint32_t s, const void* g) {
    asm volatile("cp.async.cg.shared.global [%0], [%1], 16;\n" :: "r"(s), "l"(g));
}
__device__ __forceinline__ void ldsm4(uint32_t (&r)[4], uint32_t a) {
    asm volatile("ldmatrix.sync.aligned.m8n8.x4.shared.b16 {%0,%1,%2,%3}, [%4];\n"
                 : "=r"(r[0]), "=r"(r[1]), "=r"(r[2]), "=r"(r[3]) : "r"(a));
}
__device__ __forceinline__ void mma16816(float (&c)[4], const uint32_t (&a)[4],
                                         uint32_t b0, uint32_t b1) {
    asm volatile(
        "mma.sync.aligned.m16n8k16.row.col.f32.f16.f16.f32 "
        "{%0,%1,%2,%3}, {%4,%5,%6,%7}, {%8,%9}, {%0,%1,%2,%3};\n"
        : "+f"(c[0]), "+f"(c[1]), "+f"(c[2]), "+f"(c[3])
        : "r"(a[0]), "r"(a[1]), "r"(a[2]), "r"(a[3]), "r"(b0), "r"(b1));
}

__global__ void __launch_bounds__(128, 2)
gemm_hmma7_kernel(const float* __restrict__ bias, float* __restrict__ out) {
    extern __shared__ __align__(128) char dsm[];

    const int tid  = threadIdx.x;
    const int lane = tid & 31;
    const int warp = tid >> 5;          // 0..3
    const int wm   = (warp & 1) * 64;
    const int wn   = (warp >> 1) * 64;

    const int m0 = blockIdx.x * 128;
    const int bb = blockIdx.y >> 7;
    const int oh = blockIdx.y & 127;

    const uint32_t sA = (uint32_t)__cvta_generic_to_shared(dsm);
    const uint32_t sB = sA + NSTG * A_STG;

    auto issue = [&](int kt, int s) {
        const int r   = kt >> 2;
        const int fi0 = (kt & 3) << 6;
        const int kh  = (r >= 6) ? 2 : (r >= 3 ? 1 : 0);
        const int kw  = r - kh * 3;
        const int pi  = kw * 2 + (kh & 1);
        const int dh  = kh >> 1;
        const __half* gA = g_Wh2 + (size_t)m0 * KTOT + kt * 64;
        const __half* gB = g_P2
            + (((size_t)pi * BATCH + bb) * PROWS + (oh + dh)) * ((size_t)PW * FI)
            + fi0;
        const uint32_t sa = sA + s * A_STG;
        const uint32_t sb = sB + s * B_STG;
        #pragma unroll
        for (int i = 0; i < 8; i++) {
            const int idx = (i << 7) + tid;
            const int row = idx >> 3;
            const int seg = idx & 7;
            const uint32_t so = row * 128 + ((seg ^ (row & 7)) << 4);
            cp16(sa + so, gA + (size_t)row * KTOT + seg * 8);
        }
        #pragma unroll
        for (int i = 0; i < 8; i++) {
            const int idx = (i << 7) + tid;
            const int row = idx >> 3;
            const int seg = idx & 7;
            const uint32_t so = row * 128 + ((seg ^ (row & 7)) << 4);
            cp16(sb + so, gB + (size_t)row * FI + seg * 8);
        }
        asm volatile("cp.async.commit_group;\n" ::: "memory");
    };

    float acc[4][8][4];
    #pragma unroll
    for (int i = 0; i < 4; i++)
        #pragma unroll
        for (int jj = 0; jj < 8; jj++)
            #pragma unroll
            for (int e = 0; e < 4; e++) acc[i][jj][e] = 0.0f;

    issue(0, 0); issue(1, 1);

    #pragma unroll 1
    for (int kb = 0; kb < NIT / NSTG; kb++) {
        #pragma unroll
        for (int s = 0; s < NSTG; s++) {
            const int kt = kb * NSTG + s;
            if (kt < NIT - 1)
                asm volatile("cp.async.wait_group 1;\n" ::: "memory");
            else
                asm volatile("cp.async.wait_group 0;\n" ::: "memory");
            __syncthreads();
            if (kt + 2 < NIT) issue(kt + 2, (s + 2) % NSTG);

            const uint32_t abase = sA + s * A_STG;
            const uint32_t bbase = sB + s * B_STG;

            #pragma unroll
            for (int kp = 0; kp < 2; kp++) {
                const int c0 = kp * 4;
                uint32_t br[8][4];
                #pragma unroll
                for (int nb = 0; nb < 8; nb++) {
                    const int row = wn + nb * 8 + (lane & 7);
                    const int ch  = c0 + (lane >> 3);
                    ldsm4(br[nb], bbase + row * 128 + ((ch ^ (row & 7)) << 4));
                }
                #pragma unroll
                for (int ks = 0; ks < 2; ks++) {
                    uint32_t ar[4][4];
                    #pragma unroll
                    for (int mb = 0; mb < 4; mb++) {
                        const int row = wm + mb * 16 + (lane & 15);
                        const int ch  = c0 + ks * 2 + (lane >> 4);
                        ldsm4(ar[mb], abase + row * 128 + ((ch ^ (row & 7)) << 4));
                    }
                    #pragma unroll
                    for (int mb = 0; mb < 4; mb++)
                        #pragma unroll
                        for (int nb = 0; nb < 8; nb++)
                            mma16816(acc[mb][nb], ar[mb],
                                     br[nb][ks * 2], br[nb][ks * 2 + 1]);
                }
            }
        }
    }

    // Epilogue: bias + LeakyReLU(0.2), float2 stores.
    const int g   = lane >> 2;
    const int tig = lane & 3;
    #pragma unroll
    for (int mb = 0; mb < 4; mb++) {
        const int fo = m0 + wm + mb * 16 + g;
        const float bv0 = __ldg(bias + fo);
        const float bv1 = __ldg(bias + fo + 8);
        const size_t ob0 = (((size_t)bb * FO + fo) * OHW + oh) * OHW;
        const size_t ob1 = ob0 + (size_t)8 * OHW * OHW;
        #pragma unroll
        for (int nb = 0; nb < 8; nb++) {
            const int ow = wn + nb * 8 + tig * 2;
            float v0 = acc[mb][nb][0] + bv0;
            float v1 = acc[mb][nb][1] + bv0;
            float v2 = acc[mb][nb][2] + bv1;
            float v3 = acc[mb][nb][3] + bv1;
            v0 = (v0 >= 0.0f) ? v0 : 0.2f * v0;
            v1 = (v1 >= 0.0f) ? v1 : 0.2f * v1;
            v2 = (v2 >= 0.0f) ? v2 : 0.2f * v2;
            v3 = (v3 >= 0.0f) ? v3 : 0.2f * v3;
            *reinterpret_cast<float2*>(out + ob0 + ow) = make_float2(v0, v1);
            *reinterpret_cast<float2*>(out + ob1 + ow) = make_float2(v2, v3);
        }
    }
}

// ---------------------------------------------------------------------------
// Launch
// ---------------------------------------------------------------------------
extern "C" void kernel_launch(void* const* d_in, const int* in_sizes, int n_in,
                              void* d_out, int out_size) {
    const float *x = nullptr, *w = nullptr, *b = nullptr, *fir = nullptr;
    for (int i = 0; i < n_in; i++) {
        switch (in_sizes[i]) {
            case 134217728: x   = (const float*)d_in[i]; break;  // (8,256,256,256)
            case 1179648:   w   = (const float*)d_in[i]; break;  // (512,256,3,3)
            case 512:       b   = (const float*)d_in[i]; break;  // (1,512,1,1)
            case 16:        fir = (const float*)d_in[i]; break;  // (4,4)
        }
    }
    float* out = (float*)d_out;

    cudaFuncSetAttribute(gemm_hmma7_kernel,
                         cudaFuncAttributeMaxDynamicSharedMemorySize, (int)GEMM_SMEM);

    fir9_kernel<<<dim3(17, 16, BATCH), 512>>>(x, fir);
    wcvt2_kernel<<<(FO * KTOT + 255) / 256, 256>>>(w);
    gemm_hmma7_kernel<<<dim3(4, BATCH * OHW), 128, GEMM_SMEM>>>(b, out);
}

// round 13
// speedup vs baseline: 1.0120x; 1.0120x over previous
#include <cuda_runtime.h>
#include <cuda_fp16.h>
#include <cstdint>
#include <cstddef>

// ---------------------------------------------------------------------------
// Problem constants
// ---------------------------------------------------------------------------
namespace {
constexpr int BATCH = 8;
constexpr int FI    = 256;
constexpr int FO    = 512;
constexpr int HW    = 256;     // input H = W
constexpr int OHW   = 128;     // output H = W
constexpr int KTOT  = FI * 9;  // 2304 (GEMM K, reordered k' = r*256 + fi)
constexpr int PROWS = 129;     // phase rows (h2 = 0..128)
constexpr int PW    = 128;     // phase cols (w2)
}

// Scratch (device globals; no cudaMalloc allowed).
// g_P3[pi][b][h2][fi][w2]  (w2 contiguous -> FIR writes with NO transpose;
// GEMM B tiles are [k=fi][n=w2] rows of 256B, consumed via trans-ldsm)
__device__ __half g_P3[(size_t)6 * BATCH * PROWS * FI * PW];   // ~406 MB
__device__ __half g_Wh2[(size_t)FO * KTOT];

// ---------------------------------------------------------------------------
// Pass 1 (v10): depthwise 4x4 FIR -> w2-contiguous phase planes.
// NO SMEM, NO __syncthreads. Warp = one fi channel; lanes own 8 columns.
// Per output row: 9 horizontal taps (y[0..8]) via shuffle halo; each kw plane
// gets 4 consecutive w2 halfs per lane -> one 8B coalesced store each.
// Grid (17, 32, 8): j -> rows 16j..16j+15 ; fc -> 8 fi ; b.
// ---------------------------------------------------------------------------
__device__ __forceinline__ uint32_t pack2(float a, float b) {
    __half2 h = __floats2half2_rn(a, b);
    return *reinterpret_cast<uint32_t*>(&h);
}

__global__ void __launch_bounds__(256, 3)
fir10_kernel(const float* __restrict__ x, const float* __restrict__ fir) {
    const int lane = threadIdx.x & 31;
    const int wid  = threadIdx.x >> 5;   // 0..7
    const int j  = blockIdx.x;           // 0..16 (h0 = 16j)
    const int fc = blockIdx.y;           // 0..31
    const int b  = blockIdx.z;           // 0..7
    const int h0 = 16 * j;
    const int fi = fc * 8 + wid;

    const float f0 = fir[0]  + fir[1]  + fir[2]  + fir[3];
    const float f1 = fir[4]  + fir[5]  + fir[6]  + fir[7];
    const float f2 = fir[8]  + fir[9]  + fir[10] + fir[11];
    const float f3 = fir[12] + fir[13] + fir[14] + fir[15];

    const int c8 = lane * 8;
    const float* xc = x + (size_t)(b * FI + fi) * (HW * HW);

    auto ldrow = [&](int h, float (&r)[8]) {
        if ((unsigned)h < (unsigned)HW) {
            const float4 a  = __ldg((const float4*)(xc + h * HW + c8));
            const float4 b2 = __ldg((const float4*)(xc + h * HW + c8 + 4));
            r[0]=a.x; r[1]=a.y; r[2]=a.z; r[3]=a.w;
            r[4]=b2.x; r[5]=b2.y; r[6]=b2.z; r[7]=b2.w;
        } else {
            #pragma unroll
            for (int q = 0; q < 8; q++) r[q] = 0.0f;
        }
    };

    float hist[3][8];
    ldrow(h0 - 2, hist[0]);
    ldrow(h0 - 1, hist[1]);
    ldrow(h0,     hist[2]);

    for (int p = 0; p < 8; p++) {
        const int hb = h0 + 2 * p;
        if (hb > 256) break;             // warp-uniform, no syncs in kernel
        float p1[8], p2[8];
        ldrow(hb + 1, p1);
        ldrow(hb + 2, p2);

        #pragma unroll
        for (int rr = 0; rr < 2; rr++) {
            const int h = hb + rr;
            if (h > 256) break;          // warp-uniform
            float V[8];
            #pragma unroll
            for (int q = 0; q < 8; q++) {
                V[q] = (rr == 0)
                    ? f0 * hist[0][q] + f1 * hist[1][q]
                    + f2 * hist[2][q] + f3 * p1[q]
                    : f0 * hist[1][q] + f1 * hist[2][q]
                    + f2 * p1[q]     + f3 * p2[q];
            }
            float vm2 = __shfl_up_sync(0xffffffffu, V[6], 1);
            float vm1 = __shfl_up_sync(0xffffffffu, V[7], 1);
            float vp1 = __shfl_down_sync(0xffffffffu, V[0], 1);
            float vp2 = __shfl_down_sync(0xffffffffu, V[1], 1);
            if (lane == 0)  { vm2 = 0.0f; vm1 = 0.0f; }
            if (lane == 31) { vp1 = 0.0f; vp2 = 0.0f; }
            float Vf[12];
            Vf[0] = vm2; Vf[1] = vm1;
            #pragma unroll
            for (int q = 0; q < 8; q++) Vf[2 + q] = V[q];
            Vf[10] = vp1; Vf[11] = vp2;

            float y[9];
            #pragma unroll
            for (int q = 0; q < 9; q++)
                y[q] = f0 * Vf[q] + f1 * Vf[q + 1]
                     + f2 * Vf[q + 2] + f3 * Vf[q + 3];

            const int a  = h & 1;
            const int h2 = h >> 1;
            // offset (halfs) of this warp's 256B row segment in plane pi:
            // (((pi*8+b)*129 + h2)*256 + fi)*128 + lane*4
            const size_t rowbase =
                (((size_t)b * PROWS + h2) * FI + fi) * PW + lane * 4;
            const size_t plane = (size_t)BATCH * PROWS * FI * PW;
            // kw0: y0,y2,y4,y6  (w2 = lane*4 + 0..3)
            {
                uint2 v = make_uint2(pack2(y[0], y[2]), pack2(y[4], y[6]));
                *reinterpret_cast<uint2*>(&g_P3[(size_t)(0 + a) * plane + rowbase]) = v;
            }
            // kw1: y1,y3,y5,y7
            {
                uint2 v = make_uint2(pack2(y[1], y[3]), pack2(y[5], y[7]));
                *reinterpret_cast<uint2*>(&g_P3[(size_t)(2 + a) * plane + rowbase]) = v;
            }
            // kw2: y2,y4,y6,y8   (value at w = 2*w2+2)
            {
                uint2 v = make_uint2(pack2(y[2], y[4]), pack2(y[6], y[8]));
                *reinterpret_cast<uint2*>(&g_P3[(size_t)(4 + a) * plane + rowbase]) = v;
            }
        }
        #pragma unroll
        for (int q = 0; q < 8; q++) {
            hist[0][q] = hist[2][q];
            hist[1][q] = p1[q];
            hist[2][q] = p2[q];
        }
    }
}

// ---------------------------------------------------------------------------
// Pass 1b: weights -> fp16, K reorder
// ---------------------------------------------------------------------------
__global__ void wcvt2_kernel(const float* __restrict__ w) {
    const int i = blockIdx.x * 256 + threadIdx.x;
    if (i >= FO * KTOT) return;
    const int fo = i / KTOT;
    const int k  = i - fo * KTOT;
    const int r  = k >> 8;
    const int fi = k & 255;
    g_Wh2[i] = __float2half_rn(w[((size_t)(fo * FI + fi)) * 9 + r] * (1.0f / 48.0f));
}

// ---------------------------------------------------------------------------
// Pass 2 (v11): HMMA implicit GEMM, CTA 128x128, 4 warps (64x64), BK=64,
// 3 stages, 2 CTAs/SM. A smem [m][k] swizzled (non-trans ldsm); B smem
// [k 64][n 128] pad-136 rows (trans ldsm, round-1-proven mapping).
// ---------------------------------------------------------------------------
namespace {
constexpr int NIT   = 36;
constexpr int NSTG  = 3;
constexpr int A_STG = 128 * 128;          // 16384 B
constexpr int B_STG = 64 * 136 * 2;       // 17408 B
constexpr size_t GEMM_SMEM = (size_t)NSTG * (A_STG + B_STG);  // 101376
}

__device__ __forceinline__ void cp16(uint32_t s, const void* g) {
    asm volatile("cp.async.cg.shared.global [%0], [%1], 16;\n" :: "r"(s), "l"(g));
}
__device__ __forceinline__ void ldsm4(uint32_t (&r)[4], uint32_t a) {
    asm volatile("ldmatrix.sync.aligned.m8n8.x4.shared.b16 {%0,%1,%2,%3}, [%4];\n"
                 : "=r"(r[0]), "=r"(r[1]), "=r"(r[2]), "=r"(r[3]) : "r"(a));
}
__device__ __forceinline__ void ldsm4t(uint32_t (&r)[4], uint32_t a) {
    asm volatile("ldmatrix.sync.aligned.m8n8.x4.trans.shared.b16 {%0,%1,%2,%3}, [%4];\n"
                 : "=r"(r[0]), "=r"(r[1]), "=r"(r[2]), "=r"(r[3]) : "r"(a));
}
__device__ __forceinline__ void mma16816(float (&c)[4], const uint32_t (&a)[4],
                                         uint32_t b0, uint32_t b1) {
    asm volatile(
        "mma.sync.aligned.m16n8k16.row.col.f32.f16.f16.f32 "
        "{%0,%1,%2,%3}, {%4,%5,%6,%7}, {%8,%9}, {%0,%1,%2,%3};\n"
        : "+f"(c[0]), "+f"(c[1]), "+f"(c[2]), "+f"(c[3])
        : "r"(a[0]), "r"(a[1]), "r"(a[2]), "r"(a[3]), "r"(b0), "r"(b1));
}

__global__ void __launch_bounds__(128, 2)
gemm_hmma8_kernel(const float* __restrict__ bias, float* __restrict__ out) {
    extern __shared__ __align__(128) char dsm[];

    const int tid  = threadIdx.x;
    const int lane = tid & 31;
    const int warp = tid >> 5;          // 0..3
    const int wm   = (warp & 1) * 64;
    const int wn   = (warp >> 1) * 64;

    const int m0 = blockIdx.x * 128;
    const int bb = blockIdx.y >> 7;
    const int oh = blockIdx.y & 127;

    const uint32_t sA = (uint32_t)__cvta_generic_to_shared(dsm);
    const uint32_t sB = sA + NSTG * A_STG;

    auto issue = [&](int kt, int s) {
        const int r   = kt >> 2;
        const int fi0 = (kt & 3) << 6;
        const int kh  = (r >= 6) ? 2 : (r >= 3 ? 1 : 0);
        const int kw  = r - kh * 3;
        const int pi  = kw * 2 + (kh & 1);
        const int dh  = kh >> 1;
        const __half* gA = g_Wh2 + (size_t)m0 * KTOT + kt * 64;
        const __half* gB = g_P3
            + ((((size_t)pi * BATCH + bb) * PROWS + (oh + dh)) * FI + fi0) * PW;
        const uint32_t sa = sA + s * A_STG;
        const uint32_t sb = sB + s * B_STG;
        #pragma unroll
        for (int i = 0; i < 8; i++) {               // A: 128 rows x 8 segs
            const int idx = (i << 7) + tid;
            const int row = idx >> 3;
            const int seg = idx & 7;
            const uint32_t so = row * 128 + ((seg ^ (row & 7)) << 4);
            cp16(sa + so, gA + (size_t)row * KTOT + seg * 8);
        }
        #pragma unroll
        for (int i = 0; i < 8; i++) {               // B: 64 k-rows x 16 segs
            const int idx = (i << 7) + tid;
            const int row = idx >> 4;               // k (fi) row
            const int seg = idx & 15;               // 16B seg within 256B row
            cp16(sb + row * 272 + seg * 16, gB + (size_t)row * PW + seg * 8);
        }
        asm volatile("cp.async.commit_group;\n" ::: "memory");
    };

    float acc[4][8][4];
    #pragma unroll
    for (int i = 0; i < 4; i++)
        #pragma unroll
        for (int jj = 0; jj < 8; jj++)
            #pragma unroll
            for (int e = 0; e < 4; e++) acc[i][jj][e] = 0.0f;

    issue(0, 0); issue(1, 1);

    #pragma unroll 1
    for (int kb = 0; kb < NIT / NSTG; kb++) {
        #pragma unroll
        for (int s = 0; s < NSTG; s++) {
            const int kt = kb * NSTG + s;
            if (kt < NIT - 1)
                asm volatile("cp.async.wait_group 1;\n" ::: "memory");
            else
                asm volatile("cp.async.wait_group 0;\n" ::: "memory");
            __syncthreads();
            if (kt + 2 < NIT) issue(kt + 2, (s + 2) % NSTG);

            const uint32_t abase = sA + s * A_STG;
            const uint32_t bbase = sB + s * B_STG;

            #pragma unroll
            for (int ks16 = 0; ks16 < 4; ks16++) {
                const int ko = ks16 * 16;
                // B frags via trans ldsm (round-1-proven mapping)
                uint32_t br2[8][2];
                #pragma unroll
                for (int g = 0; g < 4; g++) {
                    const int r  = ko + (lane & 15);
                    const int cn = wn + g * 16 + ((lane >> 4) << 3);
                    uint32_t t[4];
                    ldsm4t(t, bbase + (uint32_t)(r * 136 + cn) * 2);
                    br2[g * 2][0]     = t[0]; br2[g * 2][1]     = t[1];
                    br2[g * 2 + 1][0] = t[2]; br2[g * 2 + 1][1] = t[3];
                }
                // A frags (non-trans, swizzled)
                uint32_t ar[4][4];
                #pragma unroll
                for (int mb = 0; mb < 4; mb++) {
                    const int row = wm + mb * 16 + (lane & 15);
                    const int ch  = ks16 * 2 + (lane >> 4);
                    ldsm4(ar[mb], abase + row * 128 + ((ch ^ (row & 7)) << 4));
                }
                #pragma unroll
                for (int mb = 0; mb < 4; mb++)
                    #pragma unroll
                    for (int nb = 0; nb < 8; nb++)
                        mma16816(acc[mb][nb], ar[mb], br2[nb][0], br2[nb][1]);
            }
        }
    }

    // Epilogue: bias + LeakyReLU(0.2), float2 stores.
    const int g   = lane >> 2;
    const int tig = lane & 3;
    #pragma unroll
    for (int mb = 0; mb < 4; mb++) {
        const int fo = m0 + wm + mb * 16 + g;
        const float bv0 = __ldg(bias + fo);
        const float bv1 = __ldg(bias + fo + 8);
        const size_t ob0 = (((size_t)bb * FO + fo) * OHW + oh) * OHW;
        const size_t ob1 = ob0 + (size_t)8 * OHW * OHW;
        #pragma unroll
        for (int nb = 0; nb < 8; nb++) {
            const int ow = wn + nb * 8 + tig * 2;
            float v0 = acc[mb][nb][0] + bv0;
            float v1 = acc[mb][nb][1] + bv0;
            float v2 = acc[mb][nb][2] + bv1;
            float v3 = acc[mb][nb][3] + bv1;
            v0 = (v0 >= 0.0f) ? v0 : 0.2f * v0;
            v1 = (v1 >= 0.0f) ? v1 : 0.2f * v1;
            v2 = (v2 >= 0.0f) ? v2 : 0.2f * v2;
            v3 = (v3 >= 0.0f) ? v3 : 0.2f * v3;
            *reinterpret_cast<float2*>(out + ob0 + ow) = make_float2(v0, v1);
            *reinterpret_cast<float2*>(out + ob1 + ow) = make_float2(v2, v3);
        }
    }
}

// ---------------------------------------------------------------------------
// Launch
// ---------------------------------------------------------------------------
extern "C" void kernel_launch(void* const* d_in, const int* in_sizes, int n_in,
                              void* d_out, int out_size) {
    const float *x = nullptr, *w = nullptr, *b = nullptr, *fir = nullptr;
    for (int i = 0; i < n_in; i++) {
        switch (in_sizes[i]) {
            case 134217728: x   = (const float*)d_in[i]; break;  // (8,256,256,256)
            case 1179648:   w   = (const float*)d_in[i]; break;  // (512,256,3,3)
            case 512:       b   = (const float*)d_in[i]; break;  // (1,512,1,1)
            case 16:        fir = (const float*)d_in[i]; break;  // (4,4)
        }
    }
    float* out = (float*)d_out;

    cudaFuncSetAttribute(gemm_hmma8_kernel,
                         cudaFuncAttributeMaxDynamicSharedMemorySize, (int)GEMM_SMEM);

    fir10_kernel<<<dim3(17, 32, BATCH), 256>>>(x, fir);
    wcvt2_kernel<<<(FO * KTOT + 255) / 256, 256>>>(w);
    gemm_hmma8_kernel<<<dim3(4, BATCH * OHW), 128, GEMM_SMEM>>>(b, out);
}

// round 14
// speedup vs baseline: 1.0479x; 1.0355x over previous
#include <cuda_runtime.h>
#include <cuda_fp16.h>
#include <cstdint>
#include <cstddef>

// ---------------------------------------------------------------------------
// Problem constants
// ---------------------------------------------------------------------------
namespace {
constexpr int BATCH = 8;
constexpr int FI    = 256;
constexpr int FO    = 512;
constexpr int HW    = 256;     // input H = W
constexpr int OHW   = 128;     // output H = W
constexpr int KTOT  = FI * 9;  // 2304 (GEMM K, reordered k' = r*256 + fi)
constexpr int PROWS = 129;     // phase rows (h2 = 0..128)
constexpr int PW    = 128;     // phase cols (w2)
}

// Scratch (device globals; no cudaMalloc allowed).
// g_P3[pi][b][h2][fi][w2]  (w2 contiguous -> FIR writes with NO transpose;
// GEMM B tiles are [k=fi][n=w2] rows of 256B, consumed via trans-ldsm)
__device__ __half g_P3[(size_t)6 * BATCH * PROWS * FI * PW];   // ~406 MB
__device__ __half g_Wh2[(size_t)FO * KTOT];

// ---------------------------------------------------------------------------
// Pass 1 (v10, proven 145.6us @ 82.8% DRAM): transpose-free streaming FIR.
// ---------------------------------------------------------------------------
__device__ __forceinline__ uint32_t pack2(float a, float b) {
    __half2 h = __floats2half2_rn(a, b);
    return *reinterpret_cast<uint32_t*>(&h);
}

__global__ void __launch_bounds__(256, 3)
fir10_kernel(const float* __restrict__ x, const float* __restrict__ fir) {
    const int lane = threadIdx.x & 31;
    const int wid  = threadIdx.x >> 5;   // 0..7
    const int j  = blockIdx.x;           // 0..16 (h0 = 16j)
    const int fc = blockIdx.y;           // 0..31
    const int b  = blockIdx.z;           // 0..7
    const int h0 = 16 * j;
    const int fi = fc * 8 + wid;

    const float f0 = fir[0]  + fir[1]  + fir[2]  + fir[3];
    const float f1 = fir[4]  + fir[5]  + fir[6]  + fir[7];
    const float f2 = fir[8]  + fir[9]  + fir[10] + fir[11];
    const float f3 = fir[12] + fir[13] + fir[14] + fir[15];

    const int c8 = lane * 8;
    const float* xc = x + (size_t)(b * FI + fi) * (HW * HW);

    auto ldrow = [&](int h, float (&r)[8]) {
        if ((unsigned)h < (unsigned)HW) {
            const float4 a  = __ldg((const float4*)(xc + h * HW + c8));
            const float4 b2 = __ldg((const float4*)(xc + h * HW + c8 + 4));
            r[0]=a.x; r[1]=a.y; r[2]=a.z; r[3]=a.w;
            r[4]=b2.x; r[5]=b2.y; r[6]=b2.z; r[7]=b2.w;
        } else {
            #pragma unroll
            for (int q = 0; q < 8; q++) r[q] = 0.0f;
        }
    };

    float hist[3][8];
    ldrow(h0 - 2, hist[0]);
    ldrow(h0 - 1, hist[1]);
    ldrow(h0,     hist[2]);

    for (int p = 0; p < 8; p++) {
        const int hb = h0 + 2 * p;
        if (hb > 256) break;             // warp-uniform, no syncs
        float p1[8], p2[8];
        ldrow(hb + 1, p1);
        ldrow(hb + 2, p2);

        #pragma unroll
        for (int rr = 0; rr < 2; rr++) {
            const int h = hb + rr;
            if (h > 256) break;          // warp-uniform
            float V[8];
            #pragma unroll
            for (int q = 0; q < 8; q++) {
                V[q] = (rr == 0)
                    ? f0 * hist[0][q] + f1 * hist[1][q]
                    + f2 * hist[2][q] + f3 * p1[q]
                    : f0 * hist[1][q] + f1 * hist[2][q]
                    + f2 * p1[q]     + f3 * p2[q];
            }
            float vm2 = __shfl_up_sync(0xffffffffu, V[6], 1);
            float vm1 = __shfl_up_sync(0xffffffffu, V[7], 1);
            float vp1 = __shfl_down_sync(0xffffffffu, V[0], 1);
            float vp2 = __shfl_down_sync(0xffffffffu, V[1], 1);
            if (lane == 0)  { vm2 = 0.0f; vm1 = 0.0f; }
            if (lane == 31) { vp1 = 0.0f; vp2 = 0.0f; }
            float Vf[12];
            Vf[0] = vm2; Vf[1] = vm1;
            #pragma unroll
            for (int q = 0; q < 8; q++) Vf[2 + q] = V[q];
            Vf[10] = vp1; Vf[11] = vp2;

            float y[9];
            #pragma unroll
            for (int q = 0; q < 9; q++)
                y[q] = f0 * Vf[q] + f1 * Vf[q + 1]
                     + f2 * Vf[q + 2] + f3 * Vf[q + 3];

            const int a  = h & 1;
            const int h2 = h >> 1;
            const size_t rowbase =
                (((size_t)b * PROWS + h2) * FI + fi) * PW + lane * 4;
            const size_t plane = (size_t)BATCH * PROWS * FI * PW;
            {
                uint2 v = make_uint2(pack2(y[0], y[2]), pack2(y[4], y[6]));
                *reinterpret_cast<uint2*>(&g_P3[(size_t)(0 + a) * plane + rowbase]) = v;
            }
            {
                uint2 v = make_uint2(pack2(y[1], y[3]), pack2(y[5], y[7]));
                *reinterpret_cast<uint2*>(&g_P3[(size_t)(2 + a) * plane + rowbase]) = v;
            }
            {
                uint2 v = make_uint2(pack2(y[2], y[4]), pack2(y[6], y[8]));
                *reinterpret_cast<uint2*>(&g_P3[(size_t)(4 + a) * plane + rowbase]) = v;
            }
        }
        #pragma unroll
        for (int q = 0; q < 8; q++) {
            hist[0][q] = hist[2][q];
            hist[1][q] = p1[q];
            hist[2][q] = p2[q];
        }
    }
}

// ---------------------------------------------------------------------------
// Pass 1b: weights -> fp16, K reorder
// ---------------------------------------------------------------------------
__global__ void wcvt2_kernel(const float* __restrict__ w) {
    const int i = blockIdx.x * 256 + threadIdx.x;
    if (i >= FO * KTOT) return;
    const int fo = i / KTOT;
    const int k  = i - fo * KTOT;
    const int r  = k >> 8;
    const int fi = k & 255;
    g_Wh2[i] = __float2half_rn(w[((size_t)(fo * FI + fi)) * 9 + r] * (1.0f / 48.0f));
}

// ---------------------------------------------------------------------------
// Pass 2 (v12): trans-B HMMA GEMM with kp=2 grouped schedule: per k32 half,
// ALL 8 B trans-ldsm issue first (batched), then ks loop of A-ldsm + mma.
// CTA 128x128, 4 warps (64x64), BK=64, 3 stages, 2 CTAs/SM.
// ---------------------------------------------------------------------------
namespace {
constexpr int NIT   = 36;
constexpr int NSTG  = 3;
constexpr int A_STG = 128 * 128;          // 16384 B
constexpr int B_STG = 64 * 136 * 2;       // 17408 B
constexpr size_t GEMM_SMEM = (size_t)NSTG * (A_STG + B_STG);  // 101376
}

__device__ __forceinline__ void cp16(uint32_t s, const void* g) {
    asm volatile("cp.async.cg.shared.global [%0], [%1], 16;\n" :: "r"(s), "l"(g));
}
__device__ __forceinline__ void ldsm4(uint32_t (&r)[4], uint32_t a) {
    asm volatile("ldmatrix.sync.aligned.m8n8.x4.shared.b16 {%0,%1,%2,%3}, [%4];\n"
                 : "=r"(r[0]), "=r"(r[1]), "=r"(r[2]), "=r"(r[3]) : "r"(a));
}
__device__ __forceinline__ void ldsm4t(uint32_t (&r)[4], uint32_t a) {
    asm volatile("ldmatrix.sync.aligned.m8n8.x4.trans.shared.b16 {%0,%1,%2,%3}, [%4];\n"
                 : "=r"(r[0]), "=r"(r[1]), "=r"(r[2]), "=r"(r[3]) : "r"(a));
}
__device__ __forceinline__ void mma16816(float (&c)[4], const uint32_t (&a)[4],
                                         uint32_t b0, uint32_t b1) {
    asm volatile(
        "mma.sync.aligned.m16n8k16.row.col.f32.f16.f16.f32 "
        "{%0,%1,%2,%3}, {%4,%5,%6,%7}, {%8,%9}, {%0,%1,%2,%3};\n"
        : "+f"(c[0]), "+f"(c[1]), "+f"(c[2]), "+f"(c[3])
        : "r"(a[0]), "r"(a[1]), "r"(a[2]), "r"(a[3]), "r"(b0), "r"(b1));
}

__global__ void __launch_bounds__(128, 2)
gemm_hmma9_kernel(const float* __restrict__ bias, float* __restrict__ out) {
    extern __shared__ __align__(128) char dsm[];

    const int tid  = threadIdx.x;
    const int lane = tid & 31;
    const int warp = tid >> 5;          // 0..3
    const int wm   = (warp & 1) * 64;
    const int wn   = (warp >> 1) * 64;

    const int m0 = blockIdx.x * 128;
    const int bb = blockIdx.y >> 7;
    const int oh = blockIdx.y & 127;

    const uint32_t sA = (uint32_t)__cvta_generic_to_shared(dsm);
    const uint32_t sB = sA + NSTG * A_STG;

    auto issue = [&](int kt, int s) {
        const int r   = kt >> 2;
        const int fi0 = (kt & 3) << 6;
        const int kh  = (r >= 6) ? 2 : (r >= 3 ? 1 : 0);
        const int kw  = r - kh * 3;
        const int pi  = kw * 2 + (kh & 1);
        const int dh  = kh >> 1;
        const __half* gA = g_Wh2 + (size_t)m0 * KTOT + kt * 64;
        const __half* gB = g_P3
            + ((((size_t)pi * BATCH + bb) * PROWS + (oh + dh)) * FI + fi0) * PW;
        const uint32_t sa = sA + s * A_STG;
        const uint32_t sb = sB + s * B_STG;
        #pragma unroll
        for (int i = 0; i < 8; i++) {               // A: 128 rows x 8 segs
            const int idx = (i << 7) + tid;
            const int row = idx >> 3;
            const int seg = idx & 7;
            const uint32_t so = row * 128 + ((seg ^ (row & 7)) << 4);
            cp16(sa + so, gA + (size_t)row * KTOT + seg * 8);
        }
        #pragma unroll
        for (int i = 0; i < 8; i++) {               // B: 64 k-rows x 16 segs
            const int idx = (i << 7) + tid;
            const int row = idx >> 4;
            const int seg = idx & 15;
            cp16(sb + row * 272 + seg * 16, gB + (size_t)row * PW + seg * 8);
        }
        asm volatile("cp.async.commit_group;\n" ::: "memory");
    };

    float acc[4][8][4];
    #pragma unroll
    for (int i = 0; i < 4; i++)
        #pragma unroll
        for (int jj = 0; jj < 8; jj++)
            #pragma unroll
            for (int e = 0; e < 4; e++) acc[i][jj][e] = 0.0f;

    issue(0, 0); issue(1, 1);

    #pragma unroll 1
    for (int kb = 0; kb < NIT / NSTG; kb++) {
        #pragma unroll
        for (int s = 0; s < NSTG; s++) {
            const int kt = kb * NSTG + s;
            if (kt < NIT - 1)
                asm volatile("cp.async.wait_group 1;\n" ::: "memory");
            else
                asm volatile("cp.async.wait_group 0;\n" ::: "memory");
            __syncthreads();
            if (kt + 2 < NIT) issue(kt + 2, (s + 2) % NSTG);

            const uint32_t abase = sA + s * A_STG;
            const uint32_t bbase = sB + s * B_STG;

            #pragma unroll
            for (int kp = 0; kp < 2; kp++) {
                const int ko = kp * 32;
                // --- batch ALL B trans-ldsm for this k32 half ---
                uint32_t br2[2][8][2];
                #pragma unroll
                for (int hh = 0; hh < 2; hh++) {
                    #pragma unroll
                    for (int g = 0; g < 4; g++) {
                        const int r  = ko + hh * 16 + (lane & 15);
                        const int cn = wn + g * 16 + ((lane >> 4) << 3);
                        uint32_t t[4];
                        ldsm4t(t, bbase + (uint32_t)(r * 136 + cn) * 2);
                        br2[hh][g * 2][0]     = t[0]; br2[hh][g * 2][1]     = t[1];
                        br2[hh][g * 2 + 1][0] = t[2]; br2[hh][g * 2 + 1][1] = t[3];
                    }
                }
                // --- A frags + mma per k16 ---
                #pragma unroll
                for (int hh = 0; hh < 2; hh++) {
                    uint32_t ar[4][4];
                    #pragma unroll
                    for (int mb = 0; mb < 4; mb++) {
                        const int row = wm + mb * 16 + (lane & 15);
                        const int ch  = (ko >> 3) + hh * 2 + (lane >> 4);
                        ldsm4(ar[mb], abase + row * 128 + ((ch ^ (row & 7)) << 4));
                    }
                    #pragma unroll
                    for (int mb = 0; mb < 4; mb++)
                        #pragma unroll
                        for (int nb = 0; nb < 8; nb++)
                            mma16816(acc[mb][nb], ar[mb],
                                     br2[hh][nb][0], br2[hh][nb][1]);
                }
            }
        }
    }

    // Epilogue: bias + LeakyReLU(0.2), float2 stores.
    const int g   = lane >> 2;
    const int tig = lane & 3;
    #pragma unroll
    for (int mb = 0; mb < 4; mb++) {
        const int fo = m0 + wm + mb * 16 + g;
        const float bv0 = __ldg(bias + fo);
        const float bv1 = __ldg(bias + fo + 8);
        const size_t ob0 = (((size_t)bb * FO + fo) * OHW + oh) * OHW;
        const size_t ob1 = ob0 + (size_t)8 * OHW * OHW;
        #pragma unroll
        for (int nb = 0; nb < 8; nb++) {
            const int ow = wn + nb * 8 + tig * 2;
            float v0 = acc[mb][nb][0] + bv0;
            float v1 = acc[mb][nb][1] + bv0;
            float v2 = acc[mb][nb][2] + bv1;
            float v3 = acc[mb][nb][3] + bv1;
            v0 = (v0 >= 0.0f) ? v0 : 0.2f * v0;
            v1 = (v1 >= 0.0f) ? v1 : 0.2f * v1;
            v2 = (v2 >= 0.0f) ? v2 : 0.2f * v2;
            v3 = (v3 >= 0.0f) ? v3 : 0.2f * v3;
            *reinterpret_cast<float2*>(out + ob0 + ow) = make_float2(v0, v1);
            *reinterpret_cast<float2*>(out + ob1 + ow) = make_float2(v2, v3);
        }
    }
}

// ---------------------------------------------------------------------------
// Launch
// ---------------------------------------------------------------------------
extern "C" void kernel_launch(void* const* d_in, const int* in_sizes, int n_in,
                              void* d_out, int out_size) {
    const float *x = nullptr, *w = nullptr, *b = nullptr, *fir = nullptr;
    for (int i = 0; i < n_in; i++) {
        switch (in_sizes[i]) {
            case 134217728: x   = (const float*)d_in[i]; break;  // (8,256,256,256)
            case 1179648:   w   = (const float*)d_in[i]; break;  // (512,256,3,3)
            case 512:       b   = (const float*)d_in[i]; break;  // (1,512,1,1)
            case 16:        fir = (const float*)d_in[i]; break;  // (4,4)
        }
    }
    float* out = (float*)d_out;

    cudaFuncSetAttribute(gemm_hmma9_kernel,
                         cudaFuncAttributeMaxDynamicSharedMemorySize, (int)GEMM_SMEM);

    fir10_kernel<<<dim3(17, 32, BATCH), 256>>>(x, fir);
    wcvt2_kernel<<<(FO * KTOT + 255) / 256, 256>>>(w);
    gemm_hmma9_kernel<<<dim3(4, BATCH * OHW), 128, GEMM_SMEM>>>(b, out);
}

// round 15
// speedup vs baseline: 1.0762x; 1.0271x over previous
#include <cuda_runtime.h>
#include <cuda_fp16.h>
#include <cstdint>
#include <cstddef>

// ---------------------------------------------------------------------------
// Problem constants
// ---------------------------------------------------------------------------
namespace {
constexpr int BATCH = 8;
constexpr int FI    = 256;
constexpr int FO    = 512;
constexpr int HW    = 256;     // input H = W
constexpr int OHW   = 128;     // output H = W
constexpr int KTOT  = FI * 9;  // 2304 (GEMM K, reordered k' = r*256 + fi)
constexpr int PROWS = 129;     // phase rows (h2 = 0..128)
constexpr int PW    = 128;     // phase cols (w2)
}

// Scratch (device globals; no cudaMalloc allowed).
// g_P3[pi][b][h2][fi][w2]  (w2 contiguous -> FIR writes with NO transpose;
// GEMM B tiles are [k=fi][n=w2] rows of 256B, consumed via trans-ldsm)
__device__ __half g_P3[(size_t)6 * BATCH * PROWS * FI * PW];   // ~406 MB
__device__ __half g_Wh2[(size_t)FO * KTOT];

// ---------------------------------------------------------------------------
// Pass 1 (v10, proven 145.6us @ 82.8% DRAM): transpose-free streaming FIR.
// ---------------------------------------------------------------------------
__device__ __forceinline__ uint32_t pack2(float a, float b) {
    __half2 h = __floats2half2_rn(a, b);
    return *reinterpret_cast<uint32_t*>(&h);
}

__global__ void __launch_bounds__(256, 3)
fir10_kernel(const float* __restrict__ x, const float* __restrict__ fir) {
    const int lane = threadIdx.x & 31;
    const int wid  = threadIdx.x >> 5;   // 0..7
    const int j  = blockIdx.x;           // 0..16 (h0 = 16j)
    const int fc = blockIdx.y;           // 0..31
    const int b  = blockIdx.z;           // 0..7
    const int h0 = 16 * j;
    const int fi = fc * 8 + wid;

    const float f0 = fir[0]  + fir[1]  + fir[2]  + fir[3];
    const float f1 = fir[4]  + fir[5]  + fir[6]  + fir[7];
    const float f2 = fir[8]  + fir[9]  + fir[10] + fir[11];
    const float f3 = fir[12] + fir[13] + fir[14] + fir[15];

    const int c8 = lane * 8;
    const float* xc = x + (size_t)(b * FI + fi) * (HW * HW);

    auto ldrow = [&](int h, float (&r)[8]) {
        if ((unsigned)h < (unsigned)HW) {
            const float4 a  = __ldg((const float4*)(xc + h * HW + c8));
            const float4 b2 = __ldg((const float4*)(xc + h * HW + c8 + 4));
            r[0]=a.x; r[1]=a.y; r[2]=a.z; r[3]=a.w;
            r[4]=b2.x; r[5]=b2.y; r[6]=b2.z; r[7]=b2.w;
        } else {
            #pragma unroll
            for (int q = 0; q < 8; q++) r[q] = 0.0f;
        }
    };

    float hist[3][8];
    ldrow(h0 - 2, hist[0]);
    ldrow(h0 - 1, hist[1]);
    ldrow(h0,     hist[2]);

    for (int p = 0; p < 8; p++) {
        const int hb = h0 + 2 * p;
        if (hb > 256) break;             // warp-uniform, no syncs
        float p1[8], p2[8];
        ldrow(hb + 1, p1);
        ldrow(hb + 2, p2);

        #pragma unroll
        for (int rr = 0; rr < 2; rr++) {
            const int h = hb + rr;
            if (h > 256) break;          // warp-uniform
            float V[8];
            #pragma unroll
            for (int q = 0; q < 8; q++) {
                V[q] = (rr == 0)
                    ? f0 * hist[0][q] + f1 * hist[1][q]
                    + f2 * hist[2][q] + f3 * p1[q]
                    : f0 * hist[1][q] + f1 * hist[2][q]
                    + f2 * p1[q]     + f3 * p2[q];
            }
            float vm2 = __shfl_up_sync(0xffffffffu, V[6], 1);
            float vm1 = __shfl_up_sync(0xffffffffu, V[7], 1);
            float vp1 = __shfl_down_sync(0xffffffffu, V[0], 1);
            float vp2 = __shfl_down_sync(0xffffffffu, V[1], 1);
            if (lane == 0)  { vm2 = 0.0f; vm1 = 0.0f; }
            if (lane == 31) { vp1 = 0.0f; vp2 = 0.0f; }
            float Vf[12];
            Vf[0] = vm2; Vf[1] = vm1;
            #pragma unroll
            for (int q = 0; q < 8; q++) Vf[2 + q] = V[q];
            Vf[10] = vp1; Vf[11] = vp2;

            float y[9];
            #pragma unroll
            for (int q = 0; q < 9; q++)
                y[q] = f0 * Vf[q] + f1 * Vf[q + 1]
                     + f2 * Vf[q + 2] + f3 * Vf[q + 3];

            const int a  = h & 1;
            const int h2 = h >> 1;
            const size_t rowbase =
                (((size_t)b * PROWS + h2) * FI + fi) * PW + lane * 4;
            const size_t plane = (size_t)BATCH * PROWS * FI * PW;
            {
                uint2 v = make_uint2(pack2(y[0], y[2]), pack2(y[4], y[6]));
                *reinterpret_cast<uint2*>(&g_P3[(size_t)(0 + a) * plane + rowbase]) = v;
            }
            {
                uint2 v = make_uint2(pack2(y[1], y[3]), pack2(y[5], y[7]));
                *reinterpret_cast<uint2*>(&g_P3[(size_t)(2 + a) * plane + rowbase]) = v;
            }
            {
                uint2 v = make_uint2(pack2(y[2], y[4]), pack2(y[6], y[8]));
                *reinterpret_cast<uint2*>(&g_P3[(size_t)(4 + a) * plane + rowbase]) = v;
            }
        }
        #pragma unroll
        for (int q = 0; q < 8; q++) {
            hist[0][q] = hist[2][q];
            hist[1][q] = p1[q];
            hist[2][q] = p2[q];
        }
    }
}

// ---------------------------------------------------------------------------
// Pass 1b: weights -> fp16, K reorder
// ---------------------------------------------------------------------------
__global__ void wcvt2_kernel(const float* __restrict__ w) {
    const int i = blockIdx.x * 256 + threadIdx.x;
    if (i >= FO * KTOT) return;
    const int fo = i / KTOT;
    const int k  = i - fo * KTOT;
    const int r  = k >> 8;
    const int fi = k & 255;
    g_Wh2[i] = __float2half_rn(w[((size_t)(fo * FI + fi)) * 9 + r] * (1.0f / 48.0f));
}

// ---------------------------------------------------------------------------
// Pass 2 (v13): trans-B HMMA GEMM; ALL 16 B trans-ldsm for the kt batched
// up-front (one LSU burst), then cp.async issue, then 4x(A-ldsm + 32 mma)
// against resident B regs. CTA 128x128, 4 warps (64x64), BK=64, 3 stages,
// 2 CTAs/SM.
// ---------------------------------------------------------------------------
namespace {
constexpr int NIT   = 36;
constexpr int NSTG  = 3;
constexpr int A_STG = 128 * 128;          // 16384 B
constexpr int B_STG = 64 * 136 * 2;       // 17408 B
constexpr size_t GEMM_SMEM = (size_t)NSTG * (A_STG + B_STG);  // 101376
}

__device__ __forceinline__ void cp16(uint32_t s, const void* g) {
    asm volatile("cp.async.cg.shared.global [%0], [%1], 16;\n" :: "r"(s), "l"(g));
}
__device__ __forceinline__ void ldsm4(uint32_t (&r)[4], uint32_t a) {
    asm volatile("ldmatrix.sync.aligned.m8n8.x4.shared.b16 {%0,%1,%2,%3}, [%4];\n"
                 : "=r"(r[0]), "=r"(r[1]), "=r"(r[2]), "=r"(r[3]) : "r"(a));
}
__device__ __forceinline__ void ldsm4t(uint32_t (&r)[4], uint32_t a) {
    asm volatile("ldmatrix.sync.aligned.m8n8.x4.trans.shared.b16 {%0,%1,%2,%3}, [%4];\n"
                 : "=r"(r[0]), "=r"(r[1]), "=r"(r[2]), "=r"(r[3]) : "r"(a));
}
__device__ __forceinline__ void mma16816(float (&c)[4], const uint32_t (&a)[4],
                                         uint32_t b0, uint32_t b1) {
    asm volatile(
        "mma.sync.aligned.m16n8k16.row.col.f32.f16.f16.f32 "
        "{%0,%1,%2,%3}, {%4,%5,%6,%7}, {%8,%9}, {%0,%1,%2,%3};\n"
        : "+f"(c[0]), "+f"(c[1]), "+f"(c[2]), "+f"(c[3])
        : "r"(a[0]), "r"(a[1]), "r"(a[2]), "r"(a[3]), "r"(b0), "r"(b1));
}

__global__ void __launch_bounds__(128, 2)
gemm_hmma10_kernel(const float* __restrict__ bias, float* __restrict__ out) {
    extern __shared__ __align__(128) char dsm[];

    const int tid  = threadIdx.x;
    const int lane = tid & 31;
    const int warp = tid >> 5;          // 0..3
    const int wm   = (warp & 1) * 64;
    const int wn   = (warp >> 1) * 64;

    const int m0 = blockIdx.x * 128;
    const int bb = blockIdx.y >> 7;
    const int oh = blockIdx.y & 127;

    const uint32_t sA = (uint32_t)__cvta_generic_to_shared(dsm);
    const uint32_t sB = sA + NSTG * A_STG;

    auto issue = [&](int kt, int s) {
        const int r   = kt >> 2;
        const int fi0 = (kt & 3) << 6;
        const int kh  = (r >= 6) ? 2 : (r >= 3 ? 1 : 0);
        const int kw  = r - kh * 3;
        const int pi  = kw * 2 + (kh & 1);
        const int dh  = kh >> 1;
        const __half* gA = g_Wh2 + (size_t)m0 * KTOT + kt * 64;
        const __half* gB = g_P3
            + ((((size_t)pi * BATCH + bb) * PROWS + (oh + dh)) * FI + fi0) * PW;
        const uint32_t sa = sA + s * A_STG;
        const uint32_t sb = sB + s * B_STG;
        #pragma unroll
        for (int i = 0; i < 8; i++) {               // A: 128 rows x 8 segs
            const int idx = (i << 7) + tid;
            const int row = idx >> 3;
            const int seg = idx & 7;
            const uint32_t so = row * 128 + ((seg ^ (row & 7)) << 4);
            cp16(sa + so, gA + (size_t)row * KTOT + seg * 8);
        }
        #pragma unroll
        for (int i = 0; i < 8; i++) {               // B: 64 k-rows x 16 segs
            const int idx = (i << 7) + tid;
            const int row = idx >> 4;
            const int seg = idx & 15;
            cp16(sb + row * 272 + seg * 16, gB + (size_t)row * PW + seg * 8);
        }
        asm volatile("cp.async.commit_group;\n" ::: "memory");
    };

    float acc[4][8][4];
    #pragma unroll
    for (int i = 0; i < 4; i++)
        #pragma unroll
        for (int jj = 0; jj < 8; jj++)
            #pragma unroll
            for (int e = 0; e < 4; e++) acc[i][jj][e] = 0.0f;

    issue(0, 0); issue(1, 1);

    #pragma unroll 1
    for (int kb = 0; kb < NIT / NSTG; kb++) {
        #pragma unroll
        for (int s = 0; s < NSTG; s++) {
            const int kt = kb * NSTG + s;
            if (kt < NIT - 1)
                asm volatile("cp.async.wait_group 1;\n" ::: "memory");
            else
                asm volatile("cp.async.wait_group 0;\n" ::: "memory");
            __syncthreads();

            const uint32_t abase = sA + s * A_STG;
            const uint32_t bbase = sB + s * B_STG;

            // --- ALL 16 B trans-ldsm for this kt, one burst ---
            uint32_t br[4][8][2];   // [k16][nb][2]
            #pragma unroll
            for (int hh = 0; hh < 4; hh++) {
                #pragma unroll
                for (int g = 0; g < 4; g++) {
                    const int r  = hh * 16 + (lane & 15);
                    const int cn = wn + g * 16 + ((lane >> 4) << 3);
                    uint32_t t[4];
                    ldsm4t(t, bbase + (uint32_t)(r * 136 + cn) * 2);
                    br[hh][g * 2][0]     = t[0]; br[hh][g * 2][1]     = t[1];
                    br[hh][g * 2 + 1][0] = t[2]; br[hh][g * 2 + 1][1] = t[3];
                }
            }

            if (kt + 2 < NIT) issue(kt + 2, (s + 2) % NSTG);

            // --- A frags + mma per k16 against resident B regs ---
            #pragma unroll
            for (int hh = 0; hh < 4; hh++) {
                uint32_t ar[4][4];
                #pragma unroll
                for (int mb = 0; mb < 4; mb++) {
                    const int row = wm + mb * 16 + (lane & 15);
                    const int ch  = hh * 2 + (lane >> 4);
                    ldsm4(ar[mb], abase + row * 128 + ((ch ^ (row & 7)) << 4));
                }
                #pragma unroll
                for (int mb = 0; mb < 4; mb++)
                    #pragma unroll
                    for (int nb = 0; nb < 8; nb++)
                        mma16816(acc[mb][nb], ar[mb],
                                 br[hh][nb][0], br[hh][nb][1]);
            }
        }
    }

    // Epilogue: bias + LeakyReLU(0.2), float2 stores.
    const int g   = lane >> 2;
    const int tig = lane & 3;
    #pragma unroll
    for (int mb = 0; mb < 4; mb++) {
        const int fo = m0 + wm + mb * 16 + g;
        const float bv0 = __ldg(bias + fo);
        const float bv1 = __ldg(bias + fo + 8);
        const size_t ob0 = (((size_t)bb * FO + fo) * OHW + oh) * OHW;
        const size_t ob1 = ob0 + (size_t)8 * OHW * OHW;
        #pragma unroll
        for (int nb = 0; nb < 8; nb++) {
            const int ow = wn + nb * 8 + tig * 2;
            float v0 = acc[mb][nb][0] + bv0;
            float v1 = acc[mb][nb][1] + bv0;
            float v2 = acc[mb][nb][2] + bv1;
            float v3 = acc[mb][nb][3] + bv1;
            v0 = (v0 >= 0.0f) ? v0 : 0.2f * v0;
            v1 = (v1 >= 0.0f) ? v1 : 0.2f * v1;
            v2 = (v2 >= 0.0f) ? v2 : 0.2f * v2;
            v3 = (v3 >= 0.0f) ? v3 : 0.2f * v3;
            *reinterpret_cast<float2*>(out + ob0 + ow) = make_float2(v0, v1);
            *reinterpret_cast<float2*>(out + ob1 + ow) = make_float2(v2, v3);
        }
    }
}

// ---------------------------------------------------------------------------
// Launch
// ---------------------------------------------------------------------------
extern "C" void kernel_launch(void* const* d_in, const int* in_sizes, int n_in,
                              void* d_out, int out_size) {
    const float *x = nullptr, *w = nullptr, *b = nullptr, *fir = nullptr;
    for (int i = 0; i < n_in; i++) {
        switch (in_sizes[i]) {
            case 134217728: x   = (const float*)d_in[i]; break;  // (8,256,256,256)
            case 1179648:   w   = (const float*)d_in[i]; break;  // (512,256,3,3)
            case 512:       b   = (const float*)d_in[i]; break;  // (1,512,1,1)
            case 16:        fir = (const float*)d_in[i]; break;  // (4,4)
        }
    }
    float* out = (float*)d_out;

    cudaFuncSetAttribute(gemm_hmma10_kernel,
                         cudaFuncAttributeMaxDynamicSharedMemorySize, (int)GEMM_SMEM);

    fir10_kernel<<<dim3(17, 32, BATCH), 256>>>(x, fir);
    wcvt2_kernel<<<(FO * KTOT + 255) / 256, 256>>>(w);
    gemm_hmma10_kernel<<<dim3(4, BATCH * OHW), 128, GEMM_SMEM>>>(b, out);
}

// round 16
// speedup vs baseline: 1.0777x; 1.0014x over previous
#include <cuda_runtime.h>
#include <cuda_fp16.h>
#include <cstdint>
#include <cstddef>

// ---------------------------------------------------------------------------
// Problem constants
// ---------------------------------------------------------------------------
namespace {
constexpr int BATCH = 8;
constexpr int FI    = 256;
constexpr int FO    = 512;
constexpr int HW    = 256;     // input H = W
constexpr int OHW   = 128;     // output H = W
constexpr int KTOT  = FI * 9;  // 2304 (GEMM K, reordered k' = r*256 + fi)
constexpr int PROWS = 129;     // phase rows (h2 = 0..128)
constexpr int PW    = 128;     // phase cols (w2)
}

// Scratch (device globals; no cudaMalloc allowed).
// g_P3[pi][b][h2][fi][w2]  (w2 contiguous -> FIR writes with NO transpose;
// GEMM B tiles are [k=fi][n=w2] rows of 256B, consumed via trans-ldsm)
__device__ __half g_P3[(size_t)6 * BATCH * PROWS * FI * PW];   // ~406 MB
__device__ __half g_Wh2[(size_t)FO * KTOT];

// ---------------------------------------------------------------------------
// Pass 1 (v11): transpose-free streaming FIR, 32-row h-groups (halo 35/32).
// Grid (9, 32, 8): j -> rows 32j..32j+31 ; fc -> 8 fi ; b.
// ---------------------------------------------------------------------------
__device__ __forceinline__ uint32_t pack2(float a, float b) {
    __half2 h = __floats2half2_rn(a, b);
    return *reinterpret_cast<uint32_t*>(&h);
}

__global__ void __launch_bounds__(256, 3)
fir11_kernel(const float* __restrict__ x, const float* __restrict__ fir) {
    const int lane = threadIdx.x & 31;
    const int wid  = threadIdx.x >> 5;   // 0..7
    const int j  = blockIdx.x;           // 0..8 (h0 = 32j)
    const int fc = blockIdx.y;           // 0..31
    const int b  = blockIdx.z;           // 0..7
    const int h0 = 32 * j;
    const int fi = fc * 8 + wid;

    const float f0 = fir[0]  + fir[1]  + fir[2]  + fir[3];
    const float f1 = fir[4]  + fir[5]  + fir[6]  + fir[7];
    const float f2 = fir[8]  + fir[9]  + fir[10] + fir[11];
    const float f3 = fir[12] + fir[13] + fir[14] + fir[15];

    const int c8 = lane * 8;
    const float* xc = x + (size_t)(b * FI + fi) * (HW * HW);

    auto ldrow = [&](int h, float (&r)[8]) {
        if ((unsigned)h < (unsigned)HW) {
            const float4 a  = __ldg((const float4*)(xc + h * HW + c8));
            const float4 b2 = __ldg((const float4*)(xc + h * HW + c8 + 4));
            r[0]=a.x; r[1]=a.y; r[2]=a.z; r[3]=a.w;
            r[4]=b2.x; r[5]=b2.y; r[6]=b2.z; r[7]=b2.w;
        } else {
            #pragma unroll
            for (int q = 0; q < 8; q++) r[q] = 0.0f;
        }
    };

    float hist[3][8];
    ldrow(h0 - 2, hist[0]);
    ldrow(h0 - 1, hist[1]);
    ldrow(h0,     hist[2]);

    for (int p = 0; p < 16; p++) {
        const int hb = h0 + 2 * p;
        if (hb > 256) break;             // warp-uniform, no syncs
        float p1[8], p2[8];
        ldrow(hb + 1, p1);
        ldrow(hb + 2, p2);

        #pragma unroll
        for (int rr = 0; rr < 2; rr++) {
            const int h = hb + rr;
            if (h > 256) break;          // warp-uniform
            float V[8];
            #pragma unroll
            for (int q = 0; q < 8; q++) {
                V[q] = (rr == 0)
                    ? f0 * hist[0][q] + f1 * hist[1][q]
                    + f2 * hist[2][q] + f3 * p1[q]
                    : f0 * hist[1][q] + f1 * hist[2][q]
                    + f2 * p1[q]     + f3 * p2[q];
            }
            float vm2 = __shfl_up_sync(0xffffffffu, V[6], 1);
            float vm1 = __shfl_up_sync(0xffffffffu, V[7], 1);
            float vp1 = __shfl_down_sync(0xffffffffu, V[0], 1);
            float vp2 = __shfl_down_sync(0xffffffffu, V[1], 1);
            if (lane == 0)  { vm2 = 0.0f; vm1 = 0.0f; }
            if (lane == 31) { vp1 = 0.0f; vp2 = 0.0f; }
            float Vf[12];
            Vf[0] = vm2; Vf[1] = vm1;
            #pragma unroll
            for (int q = 0; q < 8; q++) Vf[2 + q] = V[q];
            Vf[10] = vp1; Vf[11] = vp2;

            float y[9];
            #pragma unroll
            for (int q = 0; q < 9; q++)
                y[q] = f0 * Vf[q] + f1 * Vf[q + 1]
                     + f2 * Vf[q + 2] + f3 * Vf[q + 3];

            const int a  = h & 1;
            const int h2 = h >> 1;
            const size_t rowbase =
                (((size_t)b * PROWS + h2) * FI + fi) * PW + lane * 4;
            const size_t plane = (size_t)BATCH * PROWS * FI * PW;
            {
                uint2 v = make_uint2(pack2(y[0], y[2]), pack2(y[4], y[6]));
                *reinterpret_cast<uint2*>(&g_P3[(size_t)(0 + a) * plane + rowbase]) = v;
            }
            {
                uint2 v = make_uint2(pack2(y[1], y[3]), pack2(y[5], y[7]));
                *reinterpret_cast<uint2*>(&g_P3[(size_t)(2 + a) * plane + rowbase]) = v;
            }
            {
                uint2 v = make_uint2(pack2(y[2], y[4]), pack2(y[6], y[8]));
                *reinterpret_cast<uint2*>(&g_P3[(size_t)(4 + a) * plane + rowbase]) = v;
            }
        }
        #pragma unroll
        for (int q = 0; q < 8; q++) {
            hist[0][q] = hist[2][q];
            hist[1][q] = p1[q];
            hist[2][q] = p2[q];
        }
    }
}

// ---------------------------------------------------------------------------
// Pass 1b: weights -> fp16, K reorder
// ---------------------------------------------------------------------------
__global__ void wcvt2_kernel(const float* __restrict__ w) {
    const int i = blockIdx.x * 256 + threadIdx.x;
    if (i >= FO * KTOT) return;
    const int fo = i / KTOT;
    const int k  = i - fo * KTOT;
    const int r  = k >> 8;
    const int fi = k & 255;
    g_Wh2[i] = __float2half_rn(w[((size_t)(fo * FI + fi)) * 9 + r] * (1.0f / 48.0f));
}

// ---------------------------------------------------------------------------
// Pass 2 (v14): trans-B HMMA GEMM; per kt: B burst (16 trans-ldsm) ->
// A(hh0)+mma(hh0) -> cp.async issue -> hh1..3. CTA 128x128, 4 warps (64x64),
// BK=64, 3 stages, 2 CTAs/SM.
// ---------------------------------------------------------------------------
namespace {
constexpr int NIT   = 36;
constexpr int NSTG  = 3;
constexpr int A_STG = 128 * 128;          // 16384 B
constexpr int B_STG = 64 * 136 * 2;       // 17408 B
constexpr size_t GEMM_SMEM = (size_t)NSTG * (A_STG + B_STG);  // 101376
}

__device__ __forceinline__ void cp16(uint32_t s, const void* g) {
    asm volatile("cp.async.cg.shared.global [%0], [%1], 16;\n" :: "r"(s), "l"(g));
}
__device__ __forceinline__ void ldsm4(uint32_t (&r)[4], uint32_t a) {
    asm volatile("ldmatrix.sync.aligned.m8n8.x4.shared.b16 {%0,%1,%2,%3}, [%4];\n"
                 : "=r"(r[0]), "=r"(r[1]), "=r"(r[2]), "=r"(r[3]) : "r"(a));
}
__device__ __forceinline__ void ldsm4t(uint32_t (&r)[4], uint32_t a) {
    asm volatile("ldmatrix.sync.aligned.m8n8.x4.trans.shared.b16 {%0,%1,%2,%3}, [%4];\n"
                 : "=r"(r[0]), "=r"(r[1]), "=r"(r[2]), "=r"(r[3]) : "r"(a));
}
__device__ __forceinline__ void mma16816(float (&c)[4], const uint32_t (&a)[4],
                                         uint32_t b0, uint32_t b1) {
    asm volatile(
        "mma.sync.aligned.m16n8k16.row.col.f32.f16.f16.f32 "
        "{%0,%1,%2,%3}, {%4,%5,%6,%7}, {%8,%9}, {%0,%1,%2,%3};\n"
        : "+f"(c[0]), "+f"(c[1]), "+f"(c[2]), "+f"(c[3])
        : "r"(a[0]), "r"(a[1]), "r"(a[2]), "r"(a[3]), "r"(b0), "r"(b1));
}

__global__ void __launch_bounds__(128, 2)
gemm_hmma11_kernel(const float* __restrict__ bias, float* __restrict__ out) {
    extern __shared__ __align__(128) char dsm[];

    const int tid  = threadIdx.x;
    const int lane = tid & 31;
    const int warp = tid >> 5;          // 0..3
    const int wm   = (warp & 1) * 64;
    const int wn   = (warp >> 1) * 64;

    const int m0 = blockIdx.x * 128;
    const int bb = blockIdx.y >> 7;
    const int oh = blockIdx.y & 127;

    const uint32_t sA = (uint32_t)__cvta_generic_to_shared(dsm);
    const uint32_t sB = sA + NSTG * A_STG;

    auto issue = [&](int kt, int s) {
        const int r   = kt >> 2;
        const int fi0 = (kt & 3) << 6;
        const int kh  = (r >= 6) ? 2 : (r >= 3 ? 1 : 0);
        const int kw  = r - kh * 3;
        const int pi  = kw * 2 + (kh & 1);
        const int dh  = kh >> 1;
        const __half* gA = g_Wh2 + (size_t)m0 * KTOT + kt * 64;
        const __half* gB = g_P3
            + ((((size_t)pi * BATCH + bb) * PROWS + (oh + dh)) * FI + fi0) * PW;
        const uint32_t sa = sA + s * A_STG;
        const uint32_t sb = sB + s * B_STG;
        #pragma unroll
        for (int i = 0; i < 8; i++) {               // A: 128 rows x 8 segs
            const int idx = (i << 7) + tid;
            const int row = idx >> 3;
            const int seg = idx & 7;
            const uint32_t so = row * 128 + ((seg ^ (row & 7)) << 4);
            cp16(sa + so, gA + (size_t)row * KTOT + seg * 8);
        }
        #pragma unroll
        for (int i = 0; i < 8; i++) {               // B: 64 k-rows x 16 segs
            const int idx = (i << 7) + tid;
            const int row = idx >> 4;
            const int seg = idx & 15;
            cp16(sb + row * 272 + seg * 16, gB + (size_t)row * PW + seg * 8);
        }
        asm volatile("cp.async.commit_group;\n" ::: "memory");
    };

    float acc[4][8][4];
    #pragma unroll
    for (int i = 0; i < 4; i++)
        #pragma unroll
        for (int jj = 0; jj < 8; jj++)
            #pragma unroll
            for (int e = 0; e < 4; e++) acc[i][jj][e] = 0.0f;

    issue(0, 0); issue(1, 1);

    #pragma unroll 1
    for (int kb = 0; kb < NIT / NSTG; kb++) {
        #pragma unroll
        for (int s = 0; s < NSTG; s++) {
            const int kt = kb * NSTG + s;
            if (kt < NIT - 1)
                asm volatile("cp.async.wait_group 1;\n" ::: "memory");
            else
                asm volatile("cp.async.wait_group 0;\n" ::: "memory");
            __syncthreads();

            const uint32_t abase = sA + s * A_STG;
            const uint32_t bbase = sB + s * B_STG;

            // --- ALL 16 B trans-ldsm for this kt, one burst ---
            uint32_t br[4][8][2];   // [k16][nb][2]
            #pragma unroll
            for (int hh = 0; hh < 4; hh++) {
                #pragma unroll
                for (int g = 0; g < 4; g++) {
                    const int r  = hh * 16 + (lane & 15);
                    const int cn = wn + g * 16 + ((lane >> 4) << 3);
                    uint32_t t[4];
                    ldsm4t(t, bbase + (uint32_t)(r * 136 + cn) * 2);
                    br[hh][g * 2][0]     = t[0]; br[hh][g * 2][1]     = t[1];
                    br[hh][g * 2 + 1][0] = t[2]; br[hh][g * 2 + 1][1] = t[3];
                }
            }

            // --- hh = 0: A frags + mma immediately (restart tensor pipe) ---
            {
                uint32_t ar[4][4];
                #pragma unroll
                for (int mb = 0; mb < 4; mb++) {
                    const int row = wm + mb * 16 + (lane & 15);
                    const int ch  = (lane >> 4);
                    ldsm4(ar[mb], abase + row * 128 + ((ch ^ (row & 7)) << 4));
                }
                #pragma unroll
                for (int mb = 0; mb < 4; mb++)
                    #pragma unroll
                    for (int nb = 0; nb < 8; nb++)
                        mma16816(acc[mb][nb], ar[mb], br[0][nb][0], br[0][nb][1]);
            }

            if (kt + 2 < NIT) issue(kt + 2, (s + 2) % NSTG);

            // --- hh = 1..3 ---
            #pragma unroll
            for (int hh = 1; hh < 4; hh++) {
                uint32_t ar[4][4];
                #pragma unroll
                for (int mb = 0; mb < 4; mb++) {
                    const int row = wm + mb * 16 + (lane & 15);
                    const int ch  = hh * 2 + (lane >> 4);
                    ldsm4(ar[mb], abase + row * 128 + ((ch ^ (row & 7)) << 4));
                }
                #pragma unroll
                for (int mb = 0; mb < 4; mb++)
                    #pragma unroll
                    for (int nb = 0; nb < 8; nb++)
                        mma16816(acc[mb][nb], ar[mb],
                                 br[hh][nb][0], br[hh][nb][1]);
            }
        }
    }

    // Epilogue: bias + LeakyReLU(0.2), float2 stores.
    const int g   = lane >> 2;
    const int tig = lane & 3;
    #pragma unroll
    for (int mb = 0; mb < 4; mb++) {
        const int fo = m0 + wm + mb * 16 + g;
        const float bv0 = __ldg(bias + fo);
        const float bv1 = __ldg(bias + fo + 8);
        const size_t ob0 = (((size_t)bb * FO + fo) * OHW + oh) * OHW;
        const size_t ob1 = ob0 + (size_t)8 * OHW * OHW;
        #pragma unroll
        for (int nb = 0; nb < 8; nb++) {
            const int ow = wn + nb * 8 + tig * 2;
            float v0 = acc[mb][nb][0] + bv0;
            float v1 = acc[mb][nb][1] + bv0;
            float v2 = acc[mb][nb][2] + bv1;
            float v3 = acc[mb][nb][3] + bv1;
            v0 = (v0 >= 0.0f) ? v0 : 0.2f * v0;
            v1 = (v1 >= 0.0f) ? v1 : 0.2f * v1;
            v2 = (v2 >= 0.0f) ? v2 : 0.2f * v2;
            v3 = (v3 >= 0.0f) ? v3 : 0.2f * v3;
            *reinterpret_cast<float2*>(out + ob0 + ow) = make_float2(v0, v1);
            *reinterpret_cast<float2*>(out + ob1 + ow) = make_float2(v2, v3);
        }
    }
}

// ---------------------------------------------------------------------------
// Launch
// ---------------------------------------------------------------------------
extern "C" void kernel_launch(void* const* d_in, const int* in_sizes, int n_in,
                              void* d_out, int out_size) {
    const float *x = nullptr, *w = nullptr, *b = nullptr, *fir = nullptr;
    for (int i = 0; i < n_in; i++) {
        switch (in_sizes[i]) {
            case 134217728: x   = (const float*)d_in[i]; break;  // (8,256,256,256)
            case 1179648:   w   = (const float*)d_in[i]; break;  // (512,256,3,3)
            case 512:       b   = (const float*)d_in[i]; break;  // (1,512,1,1)
            case 16:        fir = (const float*)d_in[i]; break;  // (4,4)
        }
    }
    float* out = (float*)d_out;

    cudaFuncSetAttribute(gemm_hmma11_kernel,
                         cudaFuncAttributeMaxDynamicSharedMemorySize, (int)GEMM_SMEM);

    fir11_kernel<<<dim3(9, 32, BATCH), 256>>>(x, fir);
    wcvt2_kernel<<<(FO * KTOT + 255) / 256, 256>>>(w);
    gemm_hmma11_kernel<<<dim3(4, BATCH * OHW), 128, GEMM_SMEM>>>(b, out);
}